// round 7
// baseline (speedup 1.0000x reference)
#include <cuda_runtime.h>
#include <cuda_bf16.h>

#define B_  16
#define M_  512
#define S_  32
#define E_  128
#define NBLK 128   // hops_fused grid: 8 segs x 16 batches (<=148 SMs: co-resident)

// Scratch (allocation-free)
__device__ float g_memory[B_ * M_ * E_];
__device__ float g_output[B_ * M_ * E_];
__device__ float g_q[B_ * E_];
__device__ float g_scores[B_ * M_];
__device__ float g_part[B_ * 8 * E_];
__device__ float g_wpart[B_ * 8 * E_];
__device__ float g_x[B_ * E_];

// software grid barrier state (returns to {0,0} after the 8 (even) barriers
// per launch -> deterministic across graph replays)
__device__ unsigned g_count = 0;
__device__ volatile unsigned g_flag = 0;

// enc[s][e] = 1 + (e-63)*(s-15)/1024

// ---------------------------------------------------------------------------
// Kernel 1: query embedding. grid B, block 128.
// ---------------------------------------------------------------------------
__global__ void __launch_bounds__(128) query_kernel(
    const int* __restrict__ queries,
    const float* __restrict__ qtab,
    int Vm1)
{
    const int b = blockIdx.x;
    const int tid = threadIdx.x;

    __shared__ int qidx[S_];
    if (tid < S_) qidx[tid] = queries[b * S_ + tid];
    __syncthreads();

    float acc = 0.f;
    const float ef = (float)(tid - 63);
    #pragma unroll
    for (int s = 0; s < S_; ++s) {
        const int idx = qidx[s];
        const float v = (idx < Vm1) ? qtab[(size_t)idx * E_ + tid] : 0.f;
        const float enc = 1.f + ef * (float)(s - 15) * (1.0f / 1024.0f);
        acc += enc * v;
    }
    g_q[b * E_ + tid] = acc;
}

// ---------------------------------------------------------------------------
// Kernel 2: story embeddings -> memory, output, fused hop-0 scores.
// grid (M, B), block 128. At the LTS roofline — irreducible gather traffic.
// ---------------------------------------------------------------------------
__global__ void __launch_bounds__(128) embed_kernel(
    const int* __restrict__ stories,
    const float* __restrict__ stab,
    const float* __restrict__ otab,
    const float* __restrict__ mbias,
    int Vm1)
{
    const int m = blockIdx.x;
    const int b = blockIdx.y;
    const int tid = threadIdx.x;

    __shared__ int sidx[S_];
    __shared__ float red[2][4][E_];
    __shared__ float qsm[E_];
    __shared__ float wsum[4];

    if (tid < S_) sidx[tid] = stories[(b * M_ + m) * S_ + tid];
    qsm[tid] = g_q[b * E_ + tid];
    __syncthreads();

    const int lane = tid & 31;
    const int grp  = tid >> 5;

    const float4* __restrict__ stab4 = reinterpret_cast<const float4*>(stab);
    const float4* __restrict__ otab4 = reinterpret_cast<const float4*>(otab);

    float am0 = 0.f, am1 = 0.f, am2 = 0.f, am3 = 0.f;
    float ao0 = 0.f, ao1 = 0.f, ao2 = 0.f, ao3 = 0.f;
    const float ef0 = (float)(lane * 4 - 63);

    #pragma unroll
    for (int it = 0; it < 8; ++it) {
        const int s = grp + it * 4;
        const int idx = sidx[s];
        float4 av = make_float4(0.f, 0.f, 0.f, 0.f);
        float4 ov = make_float4(0.f, 0.f, 0.f, 0.f);
        if (idx < Vm1) {
            const size_t ro = (size_t)idx * (E_ / 4) + lane;
            av = stab4[ro];
            ov = otab4[ro];
        }
        const float sf = (float)(s - 15) * (1.0f / 1024.0f);
        const float e0 = 1.f + ef0 * sf;
        const float e1 = 1.f + (ef0 + 1.f) * sf;
        const float e2 = 1.f + (ef0 + 2.f) * sf;
        const float e3 = 1.f + (ef0 + 3.f) * sf;
        am0 += e0 * av.x; am1 += e1 * av.y; am2 += e2 * av.z; am3 += e3 * av.w;
        ao0 += e0 * ov.x; ao1 += e1 * ov.y; ao2 += e2 * ov.z; ao3 += e3 * ov.w;
    }

    *reinterpret_cast<float4*>(&red[0][grp][lane * 4]) = make_float4(am0, am1, am2, am3);
    *reinterpret_cast<float4*>(&red[1][grp][lane * 4]) = make_float4(ao0, ao1, ao2, ao3);
    __syncthreads();

    const float mv = red[0][0][tid] + red[0][1][tid] + red[0][2][tid] + red[0][3][tid]
                   + mbias[m * E_ + tid];
    const float ov2 = red[1][0][tid] + red[1][1][tid] + red[1][2][tid] + red[1][3][tid];

    const size_t o = ((size_t)(b * M_ + m)) * E_ + tid;
    g_memory[o] = mv;
    g_output[o] = ov2;

    float sv = mv * qsm[tid];
    #pragma unroll
    for (int off = 16; off; off >>= 1)
        sv += __shfl_xor_sync(0xffffffffu, sv, off);
    if (lane == 0) wsum[grp] = sv;
    __syncthreads();
    if (tid == 0)
        g_scores[b * M_ + m] = wsum[0] + wsum[1] + wsum[2] + wsum[3];
}

// ---------------------------------------------------------------------------
// Kernel 3: ALL 3 hops in one persistent launch. grid (8, B), block 128.
// ---------------------------------------------------------------------------
__global__ void __launch_bounds__(128) hops_fused(
    const float* __restrict__ wi,
    const float* __restrict__ wo)
{
    const int b   = blockIdx.y;
    const int seg = blockIdx.x;
    const int tid = threadIdx.x;
    const int lane = tid & 31;
    const int wid = tid >> 5;

    __shared__ float q[E_];
    __shared__ float sp[M_];
    __shared__ float xs[E_];
    __shared__ float spart[4][16][33];
    __shared__ float wred[4];
    __shared__ float bc;
    __shared__ unsigned s_sense;

    if (tid == 0) s_sense = 0;
    q[tid] = g_q[b * E_ + tid];
    __syncthreads();

    // grid barrier (sense-reversing, called uniformly by all blocks)
    auto bar = [&]() {
        __syncthreads();
        if (tid == 0) {
            __threadfence();
            const unsigned target = s_sense ^ 1u;
            const unsigned old = atomicAdd(&g_count, 1u);
            if (old == (unsigned)(NBLK - 1)) {
                g_count = 0;
                __threadfence();
                g_flag = target;
            } else {
                while (g_flag != target) { }
                __threadfence();
            }
            s_sense = target;
        }
        __syncthreads();
    };

    for (int hop = 0; hop < 3; ++hop) {
        const float* __restrict__ W = (hop == 2) ? wo : wi;

        if (hop > 0) {
            // --- scores for this seg's 64 m rows (smem-transpose reduce) ---
            const float q0 = q[lane];
            const float q1 = q[lane + 32];
            const float q2 = q[lane + 64];
            const float q3 = q[lane + 96];
            const float* __restrict__ mem =
                g_memory + ((size_t)b * M_ + seg * 64 + wid * 16) * E_;
            #pragma unroll
            for (int i = 0; i < 16; ++i) {
                const float* __restrict__ r = mem + i * E_;
                spart[wid][i][lane] = r[lane] * q0 + r[lane + 32] * q1
                                    + r[lane + 64] * q2 + r[lane + 96] * q3;
            }
            __syncwarp();
            if (lane < 16) {
                float s = 0.f;
                #pragma unroll
                for (int l = 0; l < 32; ++l) s += spart[wid][lane][l];
                g_scores[b * M_ + seg * 64 + wid * 16 + lane] = s;
            }
            bar();
        }

        // --- softmax (redundant per block) ---
        const float* __restrict__ scores = g_scores + b * M_;
        const float s0 = scores[tid];
        const float s1 = scores[tid + 128];
        const float s2 = scores[tid + 256];
        const float s3 = scores[tid + 384];

        float lm = fmaxf(fmaxf(s0, s1), fmaxf(s2, s3));
        #pragma unroll
        for (int off = 16; off; off >>= 1)
            lm = fmaxf(lm, __shfl_xor_sync(0xffffffffu, lm, off));
        if (lane == 0) wred[wid] = lm;
        __syncthreads();
        if (tid == 0)
            bc = fmaxf(fmaxf(wred[0], wred[1]), fmaxf(wred[2], wred[3]));
        __syncthreads();
        const float mx = bc;

        const float p0 = __expf(s0 - mx);
        const float p1 = __expf(s1 - mx);
        const float p2 = __expf(s2 - mx);
        const float p3 = __expf(s3 - mx);
        sp[tid]       = p0;
        sp[tid + 128] = p1;
        sp[tid + 256] = p2;
        sp[tid + 384] = p3;

        float ls = p0 + p1 + p2 + p3;
        #pragma unroll
        for (int off = 16; off; off >>= 1)
            ls += __shfl_xor_sync(0xffffffffu, ls, off);
        if (lane == 0) wred[wid] = ls;
        __syncthreads();
        if (tid == 0)
            bc = 1.0f / (wred[0] + wred[1] + wred[2] + wred[3]);
        __syncthreads();
        const float inv = bc;

        // --- layer_out partial for this seg's 64 m rows ---
        {
            const float* __restrict__ op =
                g_output + ((size_t)b * M_ + seg * 64) * E_ + tid;
            const float* __restrict__ pp = &sp[seg * 64];
            float acc = 0.f;
            #pragma unroll 16
            for (int m = 0; m < 64; ++m)
                acc += pp[m] * op[(size_t)m * E_];
            g_part[((size_t)b * 8 + seg) * E_ + tid] = acc * inv;
        }
        bar();

        // --- xs = q + sum of 8 partials (redundant per block) ---
        {
            float xv = q[tid];
            const float* __restrict__ pp = g_part + (size_t)b * 8 * E_ + tid;
            #pragma unroll
            for (int s = 0; s < 8; ++s) xv += pp[s * E_];
            xs[tid] = xv;
        }
        __syncthreads();

        // --- W k-slice partial: rows [seg*16, seg*16+16), fully unrolled ---
        {
            const float* __restrict__ Wc = W + (size_t)(seg * 16) * E_ + tid;
            const float* __restrict__ xp = &xs[seg * 16];
            float a = 0.f;
            #pragma unroll
            for (int k = 0; k < 16; ++k)
                a += xp[k] * Wc[(size_t)k * E_];
            g_wpart[((size_t)b * 8 + seg) * E_ + tid] = a;
        }
        bar();

        // --- rebuild q (redundant), or write final x ---
        {
            const float* __restrict__ wp = g_wpart + (size_t)b * 8 * E_ + tid;
            float nq = wp[0];
            #pragma unroll
            for (int s = 1; s < 8; ++s) nq += wp[s * E_];
            if (hop < 2) {
                q[tid] = nq;
            } else if (seg == 0) {
                g_x[b * E_ + tid] = fmaxf(nq, 0.f);
            }
        }
        __syncthreads();
    }
}

// ---------------------------------------------------------------------------
// Kernel 4: out[b,v] = relu_x[b,:] @ w_final[:,v]. unroll 16 for MLP.
// ---------------------------------------------------------------------------
__global__ void __launch_bounds__(128) final_kernel(
    const float* __restrict__ wf,
    float* __restrict__ out,
    int V)
{
    __shared__ float xsm[E_ * B_];   // xsm[e*16 + b]
    const int tid = threadIdx.x;
    for (int i = tid; i < B_ * E_; i += 128) {
        const int b = i >> 7;
        const int e = i & 127;
        xsm[e * B_ + b] = g_x[i];
    }
    __syncthreads();

    const int v = blockIdx.x * 128 + tid;
    if (v >= V) return;

    float acc[B_];
    #pragma unroll
    for (int b = 0; b < B_; ++b) acc[b] = 0.f;

    #pragma unroll 16
    for (int e = 0; e < E_; ++e) {
        const float w = wf[(size_t)e * V + v];
        const float4* xv4 = reinterpret_cast<const float4*>(xsm + e * B_);
        #pragma unroll
        for (int b4 = 0; b4 < 4; ++b4) {
            const float4 xv = xv4[b4];
            acc[b4 * 4 + 0] += xv.x * w;
            acc[b4 * 4 + 1] += xv.y * w;
            acc[b4 * 4 + 2] += xv.z * w;
            acc[b4 * 4 + 3] += xv.w * w;
        }
    }

    #pragma unroll
    for (int b = 0; b < B_; ++b)
        out[(size_t)b * V + v] = acc[b];
}

// ---------------------------------------------------------------------------
extern "C" void kernel_launch(void* const* d_in, const int* in_sizes, int n_in,
                              void* d_out, int out_size)
{
    const int*   queries = (const int*)d_in[0];
    const int*   stories = (const int*)d_in[1];
    const float* qb      = (const float*)d_in[2];
    const float* sb      = (const float*)d_in[3];
    const float* mb      = (const float*)d_in[4];
    const float* ob      = (const float*)d_in[5];
    const float* wi      = (const float*)d_in[6];
    const float* wo      = (const float*)d_in[7];
    const float* wf      = (const float*)d_in[8];

    const int Vm1 = in_sizes[2] / E_;
    const int V   = out_size / B_;

    query_kernel<<<B_, 128>>>(queries, qb, Vm1);
    embed_kernel<<<dim3(M_, B_), 128>>>(stories, sb, ob, mb, Vm1);
    hops_fused<<<dim3(8, B_), 128>>>(wi, wo);
    final_kernel<<<(V + 127) / 128, 128>>>(wf, (float*)d_out, V);
}

// round 8
// speedup vs baseline: 1.3817x; 1.3817x over previous
#include <cuda_runtime.h>
#include <cuda_bf16.h>

#define B_  16
#define M_  512
#define S_  32
#define E_  128

// Scratch (allocation-free)
__device__ float g_memory[B_ * M_ * E_];
__device__ float g_output[B_ * M_ * E_];
__device__ float g_q[B_ * E_];
__device__ float g_scores[B_ * M_];
__device__ float g_part[B_ * 8 * E_];
__device__ float g_x[B_ * E_];

// enc[s][e] = 1 + (e-63)*(s-15)/1024

// ---------------------------------------------------------------------------
// Kernel 1: query embedding. grid B, block 128.
// ---------------------------------------------------------------------------
__global__ void __launch_bounds__(128) query_kernel(
    const int* __restrict__ queries,
    const float* __restrict__ qtab,
    int Vm1)
{
    const int b = blockIdx.x;
    const int tid = threadIdx.x;

    __shared__ int qidx[S_];
    if (tid < S_) qidx[tid] = queries[b * S_ + tid];
    __syncthreads();

    float acc = 0.f;
    const float ef = (float)(tid - 63);
    #pragma unroll
    for (int s = 0; s < S_; ++s) {
        const int idx = qidx[s];
        const float v = (idx < Vm1) ? qtab[(size_t)idx * E_ + tid] : 0.f;
        const float enc = 1.f + ef * (float)(s - 15) * (1.0f / 1024.0f);
        acc += enc * v;
    }
    g_q[b * E_ + tid] = acc;
}

// ---------------------------------------------------------------------------
// Kernel 2: story embeddings -> memory, output, fused hop-0 scores.
// grid (M, B), block 128. At the LTS roofline — irreducible gather traffic.
// ---------------------------------------------------------------------------
__global__ void __launch_bounds__(128) embed_kernel(
    const int* __restrict__ stories,
    const float* __restrict__ stab,
    const float* __restrict__ otab,
    const float* __restrict__ mbias,
    int Vm1)
{
    const int m = blockIdx.x;
    const int b = blockIdx.y;
    const int tid = threadIdx.x;

    __shared__ int sidx[S_];
    __shared__ float red[2][4][E_];
    __shared__ float qsm[E_];
    __shared__ float wsum[4];

    if (tid < S_) sidx[tid] = stories[(b * M_ + m) * S_ + tid];
    qsm[tid] = g_q[b * E_ + tid];
    __syncthreads();

    const int lane = tid & 31;
    const int grp  = tid >> 5;

    const float4* __restrict__ stab4 = reinterpret_cast<const float4*>(stab);
    const float4* __restrict__ otab4 = reinterpret_cast<const float4*>(otab);

    float am0 = 0.f, am1 = 0.f, am2 = 0.f, am3 = 0.f;
    float ao0 = 0.f, ao1 = 0.f, ao2 = 0.f, ao3 = 0.f;
    const float ef0 = (float)(lane * 4 - 63);

    #pragma unroll
    for (int it = 0; it < 8; ++it) {
        const int s = grp + it * 4;
        const int idx = sidx[s];
        float4 av = make_float4(0.f, 0.f, 0.f, 0.f);
        float4 ov = make_float4(0.f, 0.f, 0.f, 0.f);
        if (idx < Vm1) {
            const size_t ro = (size_t)idx * (E_ / 4) + lane;
            av = stab4[ro];
            ov = otab4[ro];
        }
        const float sf = (float)(s - 15) * (1.0f / 1024.0f);
        const float e0 = 1.f + ef0 * sf;
        const float e1 = 1.f + (ef0 + 1.f) * sf;
        const float e2 = 1.f + (ef0 + 2.f) * sf;
        const float e3 = 1.f + (ef0 + 3.f) * sf;
        am0 += e0 * av.x; am1 += e1 * av.y; am2 += e2 * av.z; am3 += e3 * av.w;
        ao0 += e0 * ov.x; ao1 += e1 * ov.y; ao2 += e2 * ov.z; ao3 += e3 * ov.w;
    }

    *reinterpret_cast<float4*>(&red[0][grp][lane * 4]) = make_float4(am0, am1, am2, am3);
    *reinterpret_cast<float4*>(&red[1][grp][lane * 4]) = make_float4(ao0, ao1, ao2, ao3);
    __syncthreads();

    const float mv = red[0][0][tid] + red[0][1][tid] + red[0][2][tid] + red[0][3][tid]
                   + mbias[m * E_ + tid];
    const float ov2 = red[1][0][tid] + red[1][1][tid] + red[1][2][tid] + red[1][3][tid];

    const size_t o = ((size_t)(b * M_ + m)) * E_ + tid;
    g_memory[o] = mv;
    g_output[o] = ov2;

    float sv = mv * qsm[tid];
    #pragma unroll
    for (int off = 16; off; off >>= 1)
        sv += __shfl_xor_sync(0xffffffffu, sv, off);
    if (lane == 0) wsum[grp] = sv;
    __syncthreads();
    if (tid == 0)
        g_scores[b * M_ + m] = wsum[0] + wsum[1] + wsum[2] + wsum[3];
}

// ---------------------------------------------------------------------------
// Kernel 3 (hops 2,3): scores[b,m] = memory[b,m,:] . q[b,:]
// grid (8, B), block 128. Shuffle-free smem reduce.
// ---------------------------------------------------------------------------
__global__ void __launch_bounds__(128) score_kernel()
{
    const int b = blockIdx.y;
    const int mbase = blockIdx.x * 64;
    const int tid = threadIdx.x;
    const int lane = tid & 31;
    const int w = tid >> 5;

    __shared__ float part[4][16][33];

    const float* __restrict__ q = g_q + b * E_;
    const float q0 = q[lane];
    const float q1 = q[lane + 32];
    const float q2 = q[lane + 64];
    const float q3 = q[lane + 96];

    const float* __restrict__ mem =
        g_memory + ((size_t)b * M_ + mbase + w * 16) * E_;

    #pragma unroll
    for (int i = 0; i < 16; ++i) {
        const float* __restrict__ r = mem + i * E_;
        part[w][i][lane] = r[lane] * q0 + r[lane + 32] * q1
                         + r[lane + 64] * q2 + r[lane + 96] * q3;
    }
    __syncwarp();

    if (lane < 16) {
        float s = 0.f;
        #pragma unroll
        for (int l = 0; l < 32; ++l) s += part[w][lane][l];
        g_scores[b * M_ + mbase + w * 16 + lane] = s;
    }
}

// ---------------------------------------------------------------------------
// Kernel 4 (per hop): softmax (redundant per block) + 64-m partial of
// layer_out. grid (8, B), block 128.
// ---------------------------------------------------------------------------
__global__ void __launch_bounds__(128) layerout_kernel()
{
    const int b = blockIdx.y;
    const int seg = blockIdx.x;
    const int tid = threadIdx.x;
    const int lane = tid & 31;
    const int wid = tid >> 5;

    __shared__ float sp[M_];
    __shared__ float wred[4];
    __shared__ float bc;

    const float* __restrict__ scores = g_scores + b * M_;
    const float s0 = scores[tid];
    const float s1 = scores[tid + 128];
    const float s2 = scores[tid + 256];
    const float s3 = scores[tid + 384];

    float lm = fmaxf(fmaxf(s0, s1), fmaxf(s2, s3));
    #pragma unroll
    for (int off = 16; off; off >>= 1)
        lm = fmaxf(lm, __shfl_xor_sync(0xffffffffu, lm, off));
    if (lane == 0) wred[wid] = lm;
    __syncthreads();
    if (tid == 0)
        bc = fmaxf(fmaxf(wred[0], wred[1]), fmaxf(wred[2], wred[3]));
    __syncthreads();
    const float mx = bc;

    const float p0 = __expf(s0 - mx);
    const float p1 = __expf(s1 - mx);
    const float p2 = __expf(s2 - mx);
    const float p3 = __expf(s3 - mx);
    sp[tid]       = p0;
    sp[tid + 128] = p1;
    sp[tid + 256] = p2;
    sp[tid + 384] = p3;

    float ls = p0 + p1 + p2 + p3;
    #pragma unroll
    for (int off = 16; off; off >>= 1)
        ls += __shfl_xor_sync(0xffffffffu, ls, off);
    if (lane == 0) wred[wid] = ls;
    __syncthreads();
    if (tid == 0)
        bc = 1.0f / (wred[0] + wred[1] + wred[2] + wred[3]);
    __syncthreads();
    const float inv = bc;

    const float* __restrict__ op =
        g_output + ((size_t)b * M_ + seg * 64) * E_ + tid;
    const float* __restrict__ pp = &sp[seg * 64];
    float acc = 0.f;
    #pragma unroll 16
    for (int m = 0; m < 64; ++m)
        acc += pp[m] * op[(size_t)m * E_];

    g_part[((size_t)b * 8 + seg) * E_ + tid] = acc * inv;
}

// ---------------------------------------------------------------------------
// Kernel 5 (per hop): combine partials + (q+layer)@W.
// grid B, block 512 — k split 4 ways, fully unrolled 32-load slices.
// ---------------------------------------------------------------------------
__global__ void __launch_bounds__(512) combine_kernel(
    const float* __restrict__ W, int last)
{
    const int b = blockIdx.x;
    const int tid = threadIdx.x;
    const int e  = tid & 127;
    const int qt = tid >> 7;

    __shared__ float xs[E_];
    __shared__ float red[512];

    if (tid < E_) {
        float xv = g_q[b * E_ + tid];
        const float* __restrict__ pp = g_part + (size_t)b * 8 * E_ + tid;
        #pragma unroll
        for (int s = 0; s < 8; ++s) xv += pp[s * E_];
        xs[tid] = xv;
    }
    __syncthreads();

    {
        const float* __restrict__ Wc = W + (size_t)(qt * 32) * E_ + e;
        const float* __restrict__ xp = &xs[qt * 32];
        float a = 0.f;
        #pragma unroll
        for (int k = 0; k < 32; ++k)
            a += xp[k] * Wc[(size_t)k * E_];
        red[tid] = a;
    }
    __syncthreads();

    if (tid < E_) {
        const float nq = red[tid] + red[tid + 128] + red[tid + 256] + red[tid + 384];
        if (last) g_x[b * E_ + tid] = fmaxf(nq, 0.f);
        else      g_q[b * E_ + tid] = nq;
    }
}

// ---------------------------------------------------------------------------
// Kernel 6: out[b,v] = relu_x[b,:] @ w_final[:,v].
// grid 250, block 512. e split 4 ways x 32 fully-unrolled loads (MLP=32),
// smem partial reduce. DRAM-bandwidth bound (~3us target).
// ---------------------------------------------------------------------------
__global__ void __launch_bounds__(512) final_kernel(
    const float* __restrict__ wf,
    float* __restrict__ out,
    int V)
{
    __shared__ float xsm[E_][B_];            // xsm[e][b]
    __shared__ float partial[4][128][B_];    // [qt][v_local][b] = 32KB

    const int tid = threadIdx.x;
    const int vl  = tid & 127;
    const int qt  = tid >> 7;

    for (int i = tid; i < B_ * E_; i += 512) {
        const int b = i >> 7;
        const int e = i & 127;
        xsm[e][b] = g_x[i];
    }
    __syncthreads();

    const int v = blockIdx.x * 128 + vl;
    if (v < V) {
        float acc[B_];
        #pragma unroll
        for (int b = 0; b < B_; ++b) acc[b] = 0.f;

        const float* __restrict__ wp = wf + (size_t)(qt * 32) * V + v;
        #pragma unroll
        for (int k = 0; k < 32; ++k) {
            const float w = wp[(size_t)k * V];
            const int e = qt * 32 + k;
            #pragma unroll
            for (int b = 0; b < B_; ++b)
                acc[b] += xsm[e][b] * w;
        }

        #pragma unroll
        for (int b4 = 0; b4 < 4; ++b4)
            *reinterpret_cast<float4*>(&partial[qt][vl][b4 * 4]) =
                make_float4(acc[b4 * 4], acc[b4 * 4 + 1],
                            acc[b4 * 4 + 2], acc[b4 * 4 + 3]);
    }
    __syncthreads();

    if (qt == 0 && v < V) {
        #pragma unroll
        for (int b = 0; b < B_; ++b) {
            const float r = partial[0][vl][b] + partial[1][vl][b]
                          + partial[2][vl][b] + partial[3][vl][b];
            out[(size_t)b * V + v] = r;
        }
    }
}

// ---------------------------------------------------------------------------
extern "C" void kernel_launch(void* const* d_in, const int* in_sizes, int n_in,
                              void* d_out, int out_size)
{
    const int*   queries = (const int*)d_in[0];
    const int*   stories = (const int*)d_in[1];
    const float* qb      = (const float*)d_in[2];
    const float* sb      = (const float*)d_in[3];
    const float* mb      = (const float*)d_in[4];
    const float* ob      = (const float*)d_in[5];
    const float* wi      = (const float*)d_in[6];
    const float* wo      = (const float*)d_in[7];
    const float* wf      = (const float*)d_in[8];

    const int Vm1 = in_sizes[2] / E_;
    const int V   = out_size / B_;

    query_kernel<<<B_, 128>>>(queries, qb, Vm1);
    embed_kernel<<<dim3(M_, B_), 128>>>(stories, sb, ob, mb, Vm1);

    for (int hop = 0; hop < 3; ++hop) {
        if (hop > 0) score_kernel<<<dim3(8, B_), 128>>>();
        layerout_kernel<<<dim3(8, B_), 128>>>();
        combine_kernel<<<B_, 512>>>(hop == 2 ? wo : wi, hop == 2 ? 1 : 0);
    }

    final_kernel<<<(V + 127) / 128, 512>>>(wf, (float*)d_out, V);
}

// round 14
// speedup vs baseline: 1.4220x; 1.0292x over previous
#include <cuda_runtime.h>
#include <cuda_bf16.h>

#define B_  16
#define M_  512
#define S_  32
#define E_  128

// Scratch (allocation-free)
__device__ float g_memory[B_ * M_ * E_];
__device__ float g_output[B_ * M_ * E_];
__device__ float g_qbuf[2][B_ * E_];     // ping-pong q state
__device__ float g_scores[B_ * M_];
__device__ float g_part[B_ * 8 * E_];
__device__ float g_x[B_ * E_];

// enc[s][e] = 1 + (e-63)*(s-15)/1024

// ---------------------------------------------------------------------------
// Kernel 1: query embedding -> g_qbuf[0]. grid B, block 128.
// ---------------------------------------------------------------------------
__global__ void __launch_bounds__(128) query_kernel(
    const int* __restrict__ queries,
    const float* __restrict__ qtab,
    int Vm1)
{
    const int b = blockIdx.x;
    const int tid = threadIdx.x;

    __shared__ int qidx[S_];
    if (tid < S_) qidx[tid] = queries[b * S_ + tid];
    __syncthreads();

    float acc = 0.f;
    const float ef = (float)(tid - 63);
    #pragma unroll
    for (int s = 0; s < S_; ++s) {
        const int idx = qidx[s];
        const float v = (idx < Vm1) ? qtab[(size_t)idx * E_ + tid] : 0.f;
        const float enc = 1.f + ef * (float)(s - 15) * (1.0f / 1024.0f);
        acc += enc * v;
    }
    g_qbuf[0][b * E_ + tid] = acc;
}

// ---------------------------------------------------------------------------
// Kernel 2: story embeddings -> memory, output, fused hop-0 scores (vs qbuf0).
// grid (M, B), block 128. At the LTS roofline — irreducible gather traffic.
// ---------------------------------------------------------------------------
__global__ void __launch_bounds__(128) embed_kernel(
    const int* __restrict__ stories,
    const float* __restrict__ stab,
    const float* __restrict__ otab,
    const float* __restrict__ mbias,
    int Vm1)
{
    const int m = blockIdx.x;
    const int b = blockIdx.y;
    const int tid = threadIdx.x;

    __shared__ int sidx[S_];
    __shared__ float red[2][4][E_];
    __shared__ float qsm[E_];
    __shared__ float wsum[4];

    if (tid < S_) sidx[tid] = stories[(b * M_ + m) * S_ + tid];
    qsm[tid] = g_qbuf[0][b * E_ + tid];
    __syncthreads();

    const int lane = tid & 31;
    const int grp  = tid >> 5;

    const float4* __restrict__ stab4 = reinterpret_cast<const float4*>(stab);
    const float4* __restrict__ otab4 = reinterpret_cast<const float4*>(otab);

    float am0 = 0.f, am1 = 0.f, am2 = 0.f, am3 = 0.f;
    float ao0 = 0.f, ao1 = 0.f, ao2 = 0.f, ao3 = 0.f;
    const float ef0 = (float)(lane * 4 - 63);

    #pragma unroll
    for (int it = 0; it < 8; ++it) {
        const int s = grp + it * 4;
        const int idx = sidx[s];
        float4 av = make_float4(0.f, 0.f, 0.f, 0.f);
        float4 ov = make_float4(0.f, 0.f, 0.f, 0.f);
        if (idx < Vm1) {
            const size_t ro = (size_t)idx * (E_ / 4) + lane;
            av = stab4[ro];
            ov = otab4[ro];
        }
        const float sf = (float)(s - 15) * (1.0f / 1024.0f);
        const float e0 = 1.f + ef0 * sf;
        const float e1 = 1.f + (ef0 + 1.f) * sf;
        const float e2 = 1.f + (ef0 + 2.f) * sf;
        const float e3 = 1.f + (ef0 + 3.f) * sf;
        am0 += e0 * av.x; am1 += e1 * av.y; am2 += e2 * av.z; am3 += e3 * av.w;
        ao0 += e0 * ov.x; ao1 += e1 * ov.y; ao2 += e2 * ov.z; ao3 += e3 * ov.w;
    }

    *reinterpret_cast<float4*>(&red[0][grp][lane * 4]) = make_float4(am0, am1, am2, am3);
    *reinterpret_cast<float4*>(&red[1][grp][lane * 4]) = make_float4(ao0, ao1, ao2, ao3);
    __syncthreads();

    const float mv = red[0][0][tid] + red[0][1][tid] + red[0][2][tid] + red[0][3][tid]
                   + mbias[m * E_ + tid];
    const float ov2 = red[1][0][tid] + red[1][1][tid] + red[1][2][tid] + red[1][3][tid];

    const size_t o = ((size_t)(b * M_ + m)) * E_ + tid;
    g_memory[o] = mv;
    g_output[o] = ov2;

    float sv = mv * qsm[tid];
    #pragma unroll
    for (int off = 16; off; off >>= 1)
        sv += __shfl_xor_sync(0xffffffffu, sv, off);
    if (lane == 0) wsum[grp] = sv;
    __syncthreads();
    if (tid == 0)
        g_scores[b * M_ + m] = wsum[0] + wsum[1] + wsum[2] + wsum[3];
}

// ---------------------------------------------------------------------------
// Kernel 3 (per hop): softmax (redundant per block) + 64-m partial of
// layer_out. grid (8, B), block 128.
// ---------------------------------------------------------------------------
__global__ void __launch_bounds__(128) layerout_kernel()
{
    const int b = blockIdx.y;
    const int seg = blockIdx.x;
    const int tid = threadIdx.x;
    const int lane = tid & 31;
    const int wid = tid >> 5;

    __shared__ float sp[M_];
    __shared__ float wred[4];
    __shared__ float bc;

    const float* __restrict__ scores = g_scores + b * M_;
    const float s0 = scores[tid];
    const float s1 = scores[tid + 128];
    const float s2 = scores[tid + 256];
    const float s3 = scores[tid + 384];

    float lm = fmaxf(fmaxf(s0, s1), fmaxf(s2, s3));
    #pragma unroll
    for (int off = 16; off; off >>= 1)
        lm = fmaxf(lm, __shfl_xor_sync(0xffffffffu, lm, off));
    if (lane == 0) wred[wid] = lm;
    __syncthreads();
    if (tid == 0)
        bc = fmaxf(fmaxf(wred[0], wred[1]), fmaxf(wred[2], wred[3]));
    __syncthreads();
    const float mx = bc;

    const float p0 = __expf(s0 - mx);
    const float p1 = __expf(s1 - mx);
    const float p2 = __expf(s2 - mx);
    const float p3 = __expf(s3 - mx);
    sp[tid]       = p0;
    sp[tid + 128] = p1;
    sp[tid + 256] = p2;
    sp[tid + 384] = p3;

    float ls = p0 + p1 + p2 + p3;
    #pragma unroll
    for (int off = 16; off; off >>= 1)
        ls += __shfl_xor_sync(0xffffffffu, ls, off);
    if (lane == 0) wred[wid] = ls;
    __syncthreads();
    if (tid == 0)
        bc = 1.0f / (wred[0] + wred[1] + wred[2] + wred[3]);
    __syncthreads();
    const float inv = bc;

    const float* __restrict__ op =
        g_output + ((size_t)b * M_ + seg * 64) * E_ + tid;
    const float* __restrict__ pp = &sp[seg * 64];
    float acc = 0.f;
    #pragma unroll 16
    for (int m = 0; m < 64; ++m)
        acc += pp[m] * op[(size_t)m * E_];

    g_part[((size_t)b * 8 + seg) * E_ + tid] = acc * inv;
}

// ---------------------------------------------------------------------------
// Kernel 4 (per hop): combine partials + (q+layer)@W (redundant per seg
// block) + next-hop score slice for this seg's 64 m rows.
// grid (8, B), block 512. q ping-pong selected by parity INSIDE device code
// (host-side &g_device_symbol is invalid — that was the R12 bug).
// ---------------------------------------------------------------------------
__global__ void __launch_bounds__(512) combine_score_kernel(
    const float* __restrict__ W,
    int par, int last)
{
    const int b   = blockIdx.y;
    const int seg = blockIdx.x;
    const int tid = threadIdx.x;
    const int e   = tid & 127;
    const int qt  = tid >> 7;
    const int lane = tid & 31;
    const int wid  = tid >> 5;

    const float* __restrict__ qin = g_qbuf[par];
    float* __restrict__ qout      = g_qbuf[par ^ 1];

    __shared__ float xs[E_];
    __shared__ float red[512];
    __shared__ float qn[E_];
    __shared__ float spart[4][16][33];

    if (tid < E_) {
        float xv = qin[b * E_ + tid];
        const float* __restrict__ pp = g_part + (size_t)b * 8 * E_ + tid;
        #pragma unroll
        for (int s = 0; s < 8; ++s) xv += pp[s * E_];
        xs[tid] = xv;
    }
    __syncthreads();

    // newq = xs @ W  (k split 4 ways, fully unrolled 32-load slices)
    {
        const float* __restrict__ Wc = W + (size_t)(qt * 32) * E_ + e;
        const float* __restrict__ xp = &xs[qt * 32];
        float a = 0.f;
        #pragma unroll
        for (int k = 0; k < 32; ++k)
            a += xp[k] * Wc[(size_t)k * E_];
        red[tid] = a;
    }
    __syncthreads();

    if (tid < E_) {
        const float nq = red[tid] + red[tid + 128] + red[tid + 256] + red[tid + 384];
        qn[tid] = nq;
        if (seg == 0) {
            if (last) g_x[b * E_ + tid] = fmaxf(nq, 0.f);
            else      qout[b * E_ + tid] = nq;
        }
    }
    __syncthreads();

    if (!last && wid < 4) {
        // scores for this seg's 64 m rows against qn (smem-transpose reduce)
        const float q0 = qn[lane];
        const float q1 = qn[lane + 32];
        const float q2 = qn[lane + 64];
        const float q3 = qn[lane + 96];
        const float* __restrict__ mem =
            g_memory + ((size_t)b * M_ + seg * 64 + wid * 16) * E_;
        #pragma unroll
        for (int i = 0; i < 16; ++i) {
            const float* __restrict__ r = mem + i * E_;
            spart[wid][i][lane] = r[lane] * q0 + r[lane + 32] * q1
                                + r[lane + 64] * q2 + r[lane + 96] * q3;
        }
        __syncwarp();
        if (lane < 16) {
            float s = 0.f;
            #pragma unroll
            for (int l = 0; l < 32; ++l) s += spart[wid][lane][l];
            g_scores[b * M_ + seg * 64 + wid * 16 + lane] = s;
        }
    }
}

// ---------------------------------------------------------------------------
// Kernel 5: out[b,v] = relu_x[b,:] @ w_final[:,v].
// grid 250, block 512. e split 4 ways x 32 fully-unrolled loads (MLP=32).
// ---------------------------------------------------------------------------
__global__ void __launch_bounds__(512) final_kernel(
    const float* __restrict__ wf,
    float* __restrict__ out,
    int V)
{
    __shared__ float xsm[E_][B_];            // xsm[e][b]
    __shared__ float partial[4][128][B_];    // [qt][v_local][b]

    const int tid = threadIdx.x;
    const int vl  = tid & 127;
    const int qt  = tid >> 7;

    for (int i = tid; i < B_ * E_; i += 512) {
        const int b = i >> 7;
        const int e = i & 127;
        xsm[e][b] = g_x[i];
    }
    __syncthreads();

    const int v = blockIdx.x * 128 + vl;
    if (v < V) {
        float acc[B_];
        #pragma unroll
        for (int b = 0; b < B_; ++b) acc[b] = 0.f;

        const float* __restrict__ wp = wf + (size_t)(qt * 32) * V + v;
        #pragma unroll
        for (int k = 0; k < 32; ++k) {
            const float w = wp[(size_t)k * V];
            const int e = qt * 32 + k;
            #pragma unroll
            for (int b = 0; b < B_; ++b)
                acc[b] += xsm[e][b] * w;
        }

        #pragma unroll
        for (int b4 = 0; b4 < 4; ++b4)
            *reinterpret_cast<float4*>(&partial[qt][vl][b4 * 4]) =
                make_float4(acc[b4 * 4], acc[b4 * 4 + 1],
                            acc[b4 * 4 + 2], acc[b4 * 4 + 3]);
    }
    __syncthreads();

    if (qt == 0 && v < V) {
        #pragma unroll
        for (int b = 0; b < B_; ++b) {
            const float r = partial[0][vl][b] + partial[1][vl][b]
                          + partial[2][vl][b] + partial[3][vl][b];
            out[(size_t)b * V + v] = r;
        }
    }
}

// ---------------------------------------------------------------------------
extern "C" void kernel_launch(void* const* d_in, const int* in_sizes, int n_in,
                              void* d_out, int out_size)
{
    const int*   queries = (const int*)d_in[0];
    const int*   stories = (const int*)d_in[1];
    const float* qb      = (const float*)d_in[2];
    const float* sb      = (const float*)d_in[3];
    const float* mb      = (const float*)d_in[4];
    const float* ob      = (const float*)d_in[5];
    const float* wi      = (const float*)d_in[6];
    const float* wo      = (const float*)d_in[7];
    const float* wf      = (const float*)d_in[8];

    const int Vm1 = in_sizes[2] / E_;
    const int V   = out_size / B_;

    query_kernel<<<B_, 128>>>(queries, qb, Vm1);
    embed_kernel<<<dim3(M_, B_), 128>>>(stories, sb, ob, mb, Vm1);

    for (int hop = 0; hop < 3; ++hop) {
        layerout_kernel<<<dim3(8, B_), 128>>>();
        // read g_qbuf[hop&1], write g_qbuf[(hop&1)^1] — resolved device-side
        combine_score_kernel<<<dim3(8, B_), 512>>>(
            hop == 2 ? wo : wi, hop & 1, hop == 2 ? 1 : 0);
    }

    final_kernel<<<(V + 127) / 128, 512>>>(wf, (float*)d_out, V);
}